// round 1
// baseline (speedup 1.0000x reference)
#include <cuda_runtime.h>

// TransD forward, fully simplified:
//   h_out = renorm(rp) * <renorm(hp), renorm(hv)> + renorm(hv)
//   rv_out = renorm(rv)
//   t_out = renorm(rp) * <renorm(tp), renorm(tv)> + renorm(tv)
// renorm(x): n = ||x||2; if n > 1: x *= 1/(n + 1e-7)
//
// One warp per sample. Each lane owns one float4 (row = 128 floats = 32 float4).
// 8 warp reductions (6 sumsq + 2 dots) via shfl_xor. No smem.

#define NB 8192
#define DV 32  // float4s per row

__device__ __forceinline__ float warp_sum(float v) {
    v += __shfl_xor_sync(0xffffffffu, v, 16);
    v += __shfl_xor_sync(0xffffffffu, v, 8);
    v += __shfl_xor_sync(0xffffffffu, v, 4);
    v += __shfl_xor_sync(0xffffffffu, v, 2);
    v += __shfl_xor_sync(0xffffffffu, v, 1);
    return v;
}

__device__ __forceinline__ float dot4(float4 a, float4 b) {
    return a.x * b.x + a.y * b.y + a.z * b.z + a.w * b.w;
}

__device__ __forceinline__ float rscale(float sumsq) {
    float n = sqrtf(sumsq);
    return (n > 1.0f) ? (1.0f / (n + 1e-7f)) : 1.0f;
}

__global__ __launch_bounds__(256) void transd_kernel(
    const float4* __restrict__ ee,   // entity_emb      [ENT*32]
    const float4* __restrict__ eep,  // entity_emb_p    [ENT*32]
    const float4* __restrict__ re,   // relation_emb    [REL*32]
    const float4* __restrict__ rep,  // relation_emb_p  [REL*32]
    const int* __restrict__ h,
    const int* __restrict__ r,
    const int* __restrict__ t,
    float4* __restrict__ out)        // [3 * NB * 32]
{
    int gwarp = (blockIdx.x * blockDim.x + threadIdx.x) >> 5;
    int lane = threadIdx.x & 31;
    if (gwarp >= NB) return;

    int hi = h[gwarp];
    int ri = r[gwarp];
    int ti = t[gwarp];

    float4 hv = ee [(long)hi * DV + lane];
    float4 hp = eep[(long)hi * DV + lane];
    float4 tv = ee [(long)ti * DV + lane];
    float4 tp = eep[(long)ti * DV + lane];
    float4 rv = re [(long)ri * DV + lane];
    float4 rp = rep[(long)ri * DV + lane];

    // 8 reductions
    float s_hv = warp_sum(dot4(hv, hv));
    float s_hp = warp_sum(dot4(hp, hp));
    float s_tv = warp_sum(dot4(tv, tv));
    float s_tp = warp_sum(dot4(tp, tp));
    float s_rv = warp_sum(dot4(rv, rv));
    float s_rp = warp_sum(dot4(rp, rp));
    float d_h  = warp_sum(dot4(hp, hv));
    float d_t  = warp_sum(dot4(tp, tv));

    float c_hv = rscale(s_hv);
    float c_hp = rscale(s_hp);
    float c_tv = rscale(s_tv);
    float c_tp = rscale(s_tp);
    float c_rv = rscale(s_rv);
    float c_rp = rscale(s_rp);

    // scaled dots
    float dh = d_h * c_hp * c_hv;   // <renorm hp, renorm hv>
    float dt = d_t * c_tp * c_tv;

    // h_out = rp*c_rp*dh + hv*c_hv
    float a_h = c_rp * dh;
    float4 ho;
    ho.x = rp.x * a_h + hv.x * c_hv;
    ho.y = rp.y * a_h + hv.y * c_hv;
    ho.z = rp.z * a_h + hv.z * c_hv;
    ho.w = rp.w * a_h + hv.w * c_hv;

    float4 ro;
    ro.x = rv.x * c_rv;
    ro.y = rv.y * c_rv;
    ro.z = rv.z * c_rv;
    ro.w = rv.w * c_rv;

    float a_t = c_rp * dt;
    float4 to;
    to.x = rp.x * a_t + tv.x * c_tv;
    to.y = rp.y * a_t + tv.y * c_tv;
    to.z = rp.z * a_t + tv.z * c_tv;
    to.w = rp.w * a_t + tv.w * c_tv;

    long base = (long)gwarp * DV + lane;
    out[base]                    = ho;  // h_out
    out[(long)NB * DV + base]    = ro;  // rv
    out[2L * NB * DV + base]     = to;  // t_out
}

extern "C" void kernel_launch(void* const* d_in, const int* in_sizes, int n_in,
                              void* d_out, int out_size) {
    const float4* ee  = (const float4*)d_in[0];
    const float4* eep = (const float4*)d_in[1];
    const float4* re  = (const float4*)d_in[2];
    const float4* rep = (const float4*)d_in[3];
    const int* h = (const int*)d_in[4];
    const int* r = (const int*)d_in[5];
    const int* t = (const int*)d_in[6];

    // 8 warps (256 threads) per block, 1 sample per warp
    int blocks = (NB * 32 + 255) / 256;
    transd_kernel<<<blocks, 256>>>(ee, eep, re, rep, h, r, t, (float4*)d_out);
}